// round 8
// baseline (speedup 1.0000x reference)
#include <cuda_runtime.h>
#include <cuda_bf16.h>
#include <mma.h>
#include <cstdint>

using namespace nvcuda;

// Problem constants
#define Qn 4
#define Kc 2048
#define Dd 256
#define Bb 8
#define Nn 8192
#define NTOK (Bb * Nn)        // 65536 tokens
#define MCHUNK (Nn / Qn)      // 2048 tokens per (b, q) chunk

// Screening GEMM tiling (wmma m16n16k16 bf16 -> f32)
#define TM 128                // tokens per block
#define TILE_N 64             // codes per tile
#define NTILE (Kc / TILE_N)   // 32 tiles
#define KSTEPS (Dd / 16)      // 16 k-steps

#define LDMAB 264             // padded leading dim (elements) for A/B smem tiles
#define LDSCR 68              // padded leading dim (floats) for score scratch

#define TAU 6e-3f             // certification margin (~12 sigma of bf16 screen noise)

// SMEM layout (bytes)
#define SCR_OFF   0
#define SCR_BYTES (8 * 16 * LDSCR * 4)              // 34816
#define A_OFF     (SCR_OFF + SCR_BYTES)             // 34816
#define A_BYTES   (TM * LDMAB * 2)                  // 67584
#define B0_OFF    (A_OFF + A_BYTES)                 // 102400
#define B_BYTES   (TILE_N * LDMAB * 2)              // 33792
#define B1_OFF    (B0_OFF + B_BYTES)                // 136192
#define SMEM_TOTAL (B1_OFF + B_BYTES)               // 169984

// Global scratch (static; no allocs)
__device__ float         g_xn[NTOK * Dd];        // normalized x, fp32 (exact rescore)
__device__ float         g_en[Qn * Kc * Dd];     // normalized embed, fp32 (exact rescore)
__device__ __nv_bfloat16 g_xnb[NTOK * Dd];       // bf16 screen copies
__device__ __nv_bfloat16 g_enb[Qn * Kc * Dd];
__device__ int g_n1, g_n2;
__device__ int g_f1tok[NTOK];
__device__ int g_f1idx[NTOK][8];
__device__ int g_f2tok[NTOK];

// ---------------------------------------------------------------------------
// cp.async helpers
// ---------------------------------------------------------------------------
__device__ __forceinline__ void cp16(uint32_t smem_addr, const void* gptr) {
    asm volatile("cp.async.ca.shared.global [%0], [%1], 16;"
                 :: "r"(smem_addr), "l"(gptr));
}
__device__ __forceinline__ void cp_commit() { asm volatile("cp.async.commit_group;"); }
template <int N>
__device__ __forceinline__ void cp_wait() { asm volatile("cp.async.wait_group %0;" :: "n"(N)); }
__device__ __forceinline__ uint32_t smem_u32(const void* p) {
    uint32_t a;
    asm("{ .reg .u64 t; cvta.to.shared.u64 t, %1; cvt.u32.u64 %0, t; }"
        : "=r"(a) : "l"(p));
    return a;
}

// ---------------------------------------------------------------------------
// Kernel 0a/0b: L2 normalize rows, EXACT reference-mimicking fp32 pipeline
// (unfused mul+add, shfl.down tree, sqrt.rn, max 1e-12, div.rn).
// DO NOT CHANGE NUMERICS. Also writes bf16 screen copies.
// ---------------------------------------------------------------------------
__global__ void l2norm_e_kernel(const float* __restrict__ embed) {
    if (blockIdx.x == 0 && threadIdx.x == 0) { g_n1 = 0; g_n2 = 0; }
    int row  = blockIdx.x * 8 + (threadIdx.x >> 5);
    int lane = threadIdx.x & 31;
    if (row >= Qn * Kc) return;
    const float* r = embed + (size_t)row * Dd;
    float v[8];
    float s = 0.f;
#pragma unroll
    for (int i = 0; i < 8; ++i) {
        v[i] = r[lane + 32 * i];
        s = __fadd_rn(s, __fmul_rn(v[i], v[i]));
    }
#pragma unroll
    for (int o = 16; o; o >>= 1)
        s = __fadd_rn(s, __shfl_down_sync(0xffffffffu, s, o));
    float total = __shfl_sync(0xffffffffu, s, 0);
    float nf = fmaxf(__fsqrt_rn(total), 1e-12f);
#pragma unroll
    for (int i = 0; i < 8; ++i) {
        float nv = __fdiv_rn(v[i], nf);
        size_t idx = (size_t)row * Dd + lane + 32 * i;
        g_en[idx]  = nv;
        g_enb[idx] = __float2bfloat16(nv);
    }
}

__global__ void l2norm_x_kernel(const float* __restrict__ x) {
    int row  = blockIdx.x * 8 + (threadIdx.x >> 5);
    int lane = threadIdx.x & 31;
    if (row >= NTOK) return;
    const float* r = x + (size_t)row * Dd;
    float v[8];
    float s = 0.f;
#pragma unroll
    for (int i = 0; i < 8; ++i) {
        v[i] = r[lane + 32 * i];
        s = __fadd_rn(s, __fmul_rn(v[i], v[i]));
    }
#pragma unroll
    for (int o = 16; o; o >>= 1)
        s = __fadd_rn(s, __shfl_down_sync(0xffffffffu, s, o));
    float total = __shfl_sync(0xffffffffu, s, 0);
    float nf = fmaxf(__fsqrt_rn(total), 1e-12f);
#pragma unroll
    for (int i = 0; i < 8; ++i) {
        float nv = __fdiv_rn(v[i], nf);
        size_t idx = (size_t)row * Dd + lane + 32 * i;
        g_xn[idx]  = nv;
        g_xnb[idx] = __float2bfloat16(nv);
    }
}

// top-8 insertion with (value desc, index asc) ordering
__device__ __forceinline__ void top8_insert(float v, int c, float* tv, int* ti) {
#pragma unroll
    for (int p = 0; p < 8; ++p) {
        bool better = (v > tv[p]) || (v == tv[p] && c < ti[p]);
        if (better) {
            float fv = tv[p]; tv[p] = v; v = fv;
            int   fc = ti[p]; ti[p] = c; c = fc;
        }
    }
}

// ---------------------------------------------------------------------------
// Kernel 1: bf16 wmma screening GEMM + top-8 + provisional outputs.
// 256 threads (8 warps); warp w owns tokens [16w, 16w+16); 32 N-tiles of 64.
// ---------------------------------------------------------------------------
__global__ void __launch_bounds__(256, 1)
pq_wmma_kernel(const float* __restrict__ embed,
               float* __restrict__ out,
               long long out_size) {
    extern __shared__ char smem[];
    float* scr = (float*)(smem + SCR_OFF);
    __nv_bfloat16* As = (__nv_bfloat16*)(smem + A_OFF);
    const uint32_t sb = smem_u32(smem);

    const int tid  = threadIdx.x;
    const int wid  = tid >> 5;
    const int lane = tid & 31;
    const int tok0 = blockIdx.x * TM;
    const int q = (tok0 % Nn) / MCHUNK;
    const __nv_bfloat16* Eb = g_enb + (size_t)q * Kc * Dd;

    // stage A (128 tokens x 256 bf16, padded rows) + B tile 0
    for (int i = tid; i < TM * 32; i += 256) {
        int row = i >> 5, seg = i & 31;
        cp16(sb + A_OFF + (uint32_t)row * (LDMAB * 2) + (uint32_t)seg * 16,
             g_xnb + (size_t)(tok0 + row) * Dd + seg * 8);
    }
    for (int i = tid; i < TILE_N * 32; i += 256) {
        int row = i >> 5, seg = i & 31;
        cp16(sb + B0_OFF + (uint32_t)row * (LDMAB * 2) + (uint32_t)seg * 16,
             Eb + (size_t)row * Dd + seg * 8);
    }
    cp_commit();
    cp_wait<0>();
    __syncthreads();

    // per-lane top-8 (lane pair (2t, 2t+1) covers token 16*wid + t, halves 0/1)
    float tv[8];
    int   ti[8];
#pragma unroll
    for (int k = 0; k < 8; ++k) { tv[k] = -3.4e38f; ti[k] = 0x7fffffff; }

    float* scr_w = scr + wid * 16 * LDSCR;

    for (int nt = 0; nt < NTILE; ++nt) {
        const int buf = nt & 1;
        const __nv_bfloat16* Bs =
            (const __nv_bfloat16*)(smem + (buf ? B1_OFF : B0_OFF));

        // prefetch B(nt+1) into the other buffer (overlaps compute)
        if (nt + 1 < NTILE) {
            uint32_t dstb = sb + ((nt + 1) & 1 ? B1_OFF : B0_OFF);
            for (int i = tid; i < TILE_N * 32; i += 256) {
                int row = i >> 5, seg = i & 31;
                cp16(dstb + (uint32_t)row * (LDMAB * 2) + (uint32_t)seg * 16,
                     Eb + (size_t)((nt + 1) * TILE_N + row) * Dd + seg * 8);
            }
            cp_commit();
        }

        // compute: 16 tokens x 64 codes per warp, K=256
        wmma::fragment<wmma::accumulator, 16, 16, 16, float> acc[4];
#pragma unroll
        for (int c = 0; c < 4; ++c) wmma::fill_fragment(acc[c], 0.0f);
#pragma unroll
        for (int ks = 0; ks < KSTEPS; ++ks) {
            wmma::fragment<wmma::matrix_a, 16, 16, 16, __nv_bfloat16,
                           wmma::row_major> a;
            wmma::load_matrix_sync(a, As + wid * 16 * LDMAB + ks * 16, LDMAB);
#pragma unroll
            for (int c = 0; c < 4; ++c) {
                wmma::fragment<wmma::matrix_b, 16, 16, 16, __nv_bfloat16,
                               wmma::col_major> b;
                wmma::load_matrix_sync(b, Bs + c * 16 * LDMAB + ks * 16, LDMAB);
                wmma::mma_sync(acc[c], a, b, acc[c]);
            }
        }

        // fold: store scores to per-warp scratch, scan into top-8
#pragma unroll
        for (int c = 0; c < 4; ++c)
            wmma::store_matrix_sync(scr_w + c * 16, acc[c], LDSCR,
                                    wmma::mem_row_major);
        __syncwarp();
        {
            const int trow = lane >> 1;          // local token 0..15
            const int half = lane & 1;           // which 32 codes
            const float* rowp = scr_w + trow * LDSCR + half * 32;
            const int cbase = nt * TILE_N + half * 32;
#pragma unroll
            for (int j = 0; j < 32; ++j) {
                float s = rowp[j];
                if (s > tv[7]) top8_insert(s, cbase + j, tv, ti);
            }
        }
        __syncwarp();

        cp_wait<0>();
        __syncthreads();   // B(nt+1) landed; scratch reuse safe next iter
    }

    // merge lane pairs (token owned by lanes 2t and 2t+1)
    {
        float sv[8]; int si[8];
#pragma unroll
        for (int k = 0; k < 8; ++k) { sv[k] = tv[k]; si[k] = ti[k]; }
#pragma unroll
        for (int k = 0; k < 8; ++k) {
            float ov = __shfl_xor_sync(0xffffffffu, sv[k], 1);
            int   oi = __shfl_xor_sync(0xffffffffu, si[k], 1);
            if (ov > tv[7] || (ov == tv[7] && oi < ti[7]))
                top8_insert(ov, oi, tv, ti);
        }
    }

    // provisional outputs + fix lists (even lane owns the token)
    if ((lane & 1) == 0) {
        int tlocal = wid * 16 + (lane >> 1);
        int token = tok0 + tlocal;
        ((int*)scr_w)[lane >> 1] = ti[0];   // bestcode, per-warp region
        long long epos = (long long)NTOK * Dd + token;
        if (epos < out_size) out[epos] = (float)ti[0];
        if (tv[0] - tv[1] < TAU) {
            if (tv[0] - tv[7] >= TAU) {
                int p = atomicAdd(&g_n1, 1);
                g_f1tok[p] = token;
#pragma unroll
                for (int k = 0; k < 8; ++k) g_f1idx[p][k] = ti[k];
            } else {
                int p = atomicAdd(&g_n2, 1);
                g_f2tok[p] = token;
            }
        }
    }
    __syncthreads();

    // gather raw codewords (coalesced)
    const float* Eqraw = embed + (size_t)q * Kc * Dd;
    for (int i = tid; i < TM * (Dd / 4); i += 256) {
        int token = i >> 6;
        int r = i & 63;
        int code = ((const int*)(scr + (token >> 4) * 16 * LDSCR))[token & 15];
        ((float4*)(out + (size_t)(tok0 + token) * Dd))[r] =
            ((const float4*)(Eqraw + (size_t)code * Dd))[r];
    }
}

// ---------------------------------------------------------------------------
// Kernel 2: exact fp32-chain rescore of the 8 screened candidates.
// Chain: sequential ascending-d __fmaf_rn over g_xn/g_en (bit-exact vs the
// validated rounds 4-6 path). Tie: lowest code index.
// ---------------------------------------------------------------------------
__global__ void fix1_kernel(const float* __restrict__ embed,
                            float* __restrict__ out) {
    int e    = blockIdx.x * 32 + (threadIdx.x >> 3);
    int slot = threadIdx.x & 7;
    bool active = (e < g_n1);
    int token = active ? g_f1tok[e] : 0;
    int code  = active ? g_f1idx[e][slot] : 0;
    int q = (token % Nn) / MCHUNK;

    const float* xr = g_xn + (size_t)token * Dd;
    const float* er = g_en + ((size_t)q * Kc + code) * Dd;
    float acc = 0.f;
#pragma unroll 8
    for (int d = 0; d < Dd; ++d) acc = __fmaf_rn(xr[d], er[d], acc);

    float v = acc;
    int   i = code;
    const unsigned m = 0xffffffffu;
#pragma unroll
    for (int o = 4; o; o >>= 1) {
        float ov = __shfl_down_sync(m, v, o);
        int   oi = __shfl_down_sync(m, i, o);
        if (ov > v || (ov == v && oi < i)) { v = ov; i = oi; }
    }
    int leader = (threadIdx.x & 31) & ~7;
    i = __shfl_sync(m, i, leader);

    if (active && i != g_f1idx[e][0]) {
        if (slot == 0) out[(long long)NTOK * Dd + token] = (float)i;
        const float4* src = (const float4*)(embed + ((size_t)q * Kc + i) * Dd);
        float4* dst = (float4*)(out + (size_t)token * Dd);
#pragma unroll
        for (int k = 0; k < 8; ++k) dst[slot + 8 * k] = src[slot + 8 * k];
    }
}

// ---------------------------------------------------------------------------
// Kernel 3: full exact rescan for the rare deep-tie tokens.
// ---------------------------------------------------------------------------
__global__ void fix2_kernel(const float* __restrict__ embed,
                            float* __restrict__ out) {
    __shared__ float xs[Dd];
    __shared__ float rv[256];
    __shared__ int   ri[256];
    for (int e = blockIdx.x; e < g_n2; e += gridDim.x) {
        __syncthreads();
        int token = g_f2tok[e];
        int q = (token % Nn) / MCHUNK;
        xs[threadIdx.x] = g_xn[(size_t)token * Dd + threadIdx.x];
        __syncthreads();

        float best = -3.4e38f;
        int   bi = 0x7fffffff;
        for (int c = threadIdx.x; c < Kc; c += 256) {
            const float* er = g_en + ((size_t)q * Kc + c) * Dd;
            float acc = 0.f;
#pragma unroll 8
            for (int d = 0; d < Dd; ++d) acc = __fmaf_rn(xs[d], er[d], acc);
            if (acc > best) { best = acc; bi = c; }   // ascending c: lowest kept
        }
        rv[threadIdx.x] = best;
        ri[threadIdx.x] = bi;
        __syncthreads();
        if (threadIdx.x == 0) {
            float v = -3.4e38f;
            int   i = 0x7fffffff;
            for (int t = 0; t < 256; ++t) {
                if (rv[t] > v || (rv[t] == v && ri[t] < i)) { v = rv[t]; i = ri[t]; }
            }
            ri[0] = i;
            out[(long long)NTOK * Dd + token] = (float)i;
        }
        __syncthreads();
        int code = ri[0];
        for (int k = threadIdx.x; k < 64; k += 256) {
            ((float4*)(out + (size_t)token * Dd))[k] =
                ((const float4*)(embed + ((size_t)q * Kc + code) * Dd))[k];
        }
    }
}

// ---------------------------------------------------------------------------
// Tail: zero-fill vq_loss (and any slack) past quantized+encoding.
// ---------------------------------------------------------------------------
__global__ void zero_tail(float* __restrict__ out, long long start, long long end) {
    long long i = start + (long long)blockIdx.x * blockDim.x + threadIdx.x;
    if (i < end) out[i] = 0.f;
}

extern "C" void kernel_launch(void* const* d_in, const int* in_sizes, int n_in,
                              void* d_out, int out_size) {
    const float* x     = (const float*)d_in[0];
    const float* embed = (const float*)d_in[1];
    if (n_in >= 2 && in_sizes[0] == Qn * Kc * Dd && in_sizes[1] == NTOK * Dd) {
        const float* t = x; x = embed; embed = t;
    }
    float* out = (float*)d_out;

    l2norm_e_kernel<<<(Qn * Kc) / 8, 256>>>(embed);   // also resets fix counters
    l2norm_x_kernel<<<NTOK / 8, 256>>>(x);

    long long tail = (long long)NTOK * Dd + NTOK;
    if ((long long)out_size > tail) {
        long long n = (long long)out_size - tail;
        int blocks = (int)((n + 255) / 256);
        zero_tail<<<blocks, 256>>>(out, tail, (long long)out_size);
    }

    cudaFuncSetAttribute(pq_wmma_kernel, cudaFuncAttributeMaxDynamicSharedMemorySize,
                         SMEM_TOTAL);
    pq_wmma_kernel<<<NTOK / TM, 256, SMEM_TOTAL>>>(embed, out, (long long)out_size);

    fix1_kernel<<<2048, 256>>>(embed, out);   // capacity 65536 entries
    fix2_kernel<<<512, 256>>>(embed, out);
}